// round 2
// baseline (speedup 1.0000x reference)
#include <cuda_runtime.h>
#include <cstdint>

// Problem constants (from reference): x[B,T,C,F] -> [B, T, 64], W[T,64,64], b[T,64]
#define T_DIM 1024
#define KSZ   64     // inner dim (C*F)
#define NSZ   64     // output features
#define BM    128    // B-rows per CTA

#define AS_STRIDE 68 // padded smem row stride (floats) -> conflict-free frag loads
#define WS_STRIDE 68

__global__ __launch_bounds__(256, 2)
void parallel_linear_tf32_kernel(const float* __restrict__ x,
                                 const float* __restrict__ W,
                                 const float* __restrict__ bias,
                                 float* __restrict__ out)
{
    extern __shared__ float smem[];
    float* sA = smem;                         // BM  x AS_STRIDE  (34816 B)
    float* sW = smem + BM * AS_STRIDE;        // NSZ x WS_STRIDE  (17408 B)
    float* sB = sW + NSZ * WS_STRIDE;         // 64 floats

    const int t   = blockIdx.y;               // timestep (group)
    const int b0  = blockIdx.x * BM;          // first batch row
    const int tid = threadIdx.x;

    // ---- cooperative load: W_t [64,64] fp32, float4, coalesced ----
    {
        const float4* Wg = reinterpret_cast<const float4*>(W + (size_t)t * (NSZ * KSZ));
        #pragma unroll
        for (int i = 0; i < 4; i++) {
            int idx = tid + i * 256;          // 0..1023 float4s
            int row = idx >> 4;               // 16 float4 per row
            int c4  = idx & 15;
            float4 v = Wg[row * 16 + c4];
            *reinterpret_cast<float4*>(&sW[row * WS_STRIDE + c4 * 4]) = v;
        }
    }
    // ---- cooperative load: X tile [128,64], rows strided by T*64 in gmem ----
    {
        const float* xg = x + ((size_t)b0 * T_DIM + t) * KSZ;
        #pragma unroll
        for (int i = 0; i < 8; i++) {
            int idx = tid + i * 256;          // 0..2047 float4s
            int row = idx >> 4;
            int c4  = idx & 15;
            float4 v = *reinterpret_cast<const float4*>(
                xg + (size_t)row * (T_DIM * KSZ) + c4 * 4);
            *reinterpret_cast<float4*>(&sA[row * AS_STRIDE + c4 * 4]) = v;
        }
    }
    if (tid < NSZ) sB[tid] = bias[t * NSZ + tid];
    __syncthreads();

    const int warp = tid >> 5;                // 0..7, owns rows [warp*16, warp*16+16)
    const int lane = tid & 31;
    const int g    = lane >> 2;               // groupID (0..7)
    const int tg   = lane & 3;                // threadID_in_group (0..3)
    const int mrow = warp * 16 + g;

    float acc[8][4];
    #pragma unroll
    for (int n = 0; n < 8; n++)
        #pragma unroll
        for (int j = 0; j < 4; j++) acc[n][j] = 0.f;

    // ---- mainloop: K=64 as 8 steps of m16n8k8 tf32 mma ----
    #pragma unroll
    for (int ks = 0; ks < 8; ks++) {
        const int k0 = ks * 8;
        // A fragment (row-major 16x8): a0(g,tg) a1(g+8,tg) a2(g,tg+4) a3(g+8,tg+4)
        float fa0 = sA[ mrow      * AS_STRIDE + k0 + tg    ];
        float fa1 = sA[(mrow + 8) * AS_STRIDE + k0 + tg    ];
        float fa2 = sA[ mrow      * AS_STRIDE + k0 + tg + 4];
        float fa3 = sA[(mrow + 8) * AS_STRIDE + k0 + tg + 4];
        uint32_t a0, a1, a2, a3;
        asm("cvt.rna.tf32.f32 %0, %1;" : "=r"(a0) : "f"(fa0));
        asm("cvt.rna.tf32.f32 %0, %1;" : "=r"(a1) : "f"(fa1));
        asm("cvt.rna.tf32.f32 %0, %1;" : "=r"(a2) : "f"(fa2));
        asm("cvt.rna.tf32.f32 %0, %1;" : "=r"(a3) : "f"(fa3));

        #pragma unroll
        for (int nt = 0; nt < 8; nt++) {
            // B fragment (col-major 8x8 of B^T): element = W[n][k]
            // b0: (k=tg,  n=g)   b1: (k=tg+4, n=g)
            const int ncol = nt * 8 + g;
            float fb0 = sW[ncol * WS_STRIDE + k0 + tg    ];
            float fb1 = sW[ncol * WS_STRIDE + k0 + tg + 4];
            uint32_t br0, br1;
            asm("cvt.rna.tf32.f32 %0, %1;" : "=r"(br0) : "f"(fb0));
            asm("cvt.rna.tf32.f32 %0, %1;" : "=r"(br1) : "f"(fb1));
            asm volatile(
                "mma.sync.aligned.m16n8k8.row.col.f32.tf32.tf32.f32 "
                "{%0,%1,%2,%3}, {%4,%5,%6,%7}, {%8,%9}, {%0,%1,%2,%3};"
                : "+f"(acc[nt][0]), "+f"(acc[nt][1]),
                  "+f"(acc[nt][2]), "+f"(acc[nt][3])
                : "r"(a0), "r"(a1), "r"(a2), "r"(a3), "r"(br0), "r"(br1));
        }
    }

    // ---- epilogue: +bias, float2 stores ----
    // C layout: c0(g,2tg) c1(g,2tg+1) c2(g+8,2tg) c3(g+8,2tg+1)
    const size_t row_stride = (size_t)T_DIM * KSZ;
    #pragma unroll
    for (int nt = 0; nt < 8; nt++) {
        const int col = nt * 8 + 2 * tg;
        const float bs0 = sB[col];
        const float bs1 = sB[col + 1];
        size_t base = ((size_t)(b0 + mrow) * T_DIM + t) * KSZ + col;
        float2 v0 = make_float2(acc[nt][0] + bs0, acc[nt][1] + bs1);
        *reinterpret_cast<float2*>(out + base) = v0;
        float2 v1 = make_float2(acc[nt][2] + bs0, acc[nt][3] + bs1);
        *reinterpret_cast<float2*>(out + base + 8 * row_stride) = v1;
    }
}

extern "C" void kernel_launch(void* const* d_in, const int* in_sizes, int n_in,
                              void* d_out, int out_size)
{
    const float* x = (const float*)d_in[0];
    const float* W = (const float*)d_in[1];
    const float* b = (const float*)d_in[2];
    float* out     = (float*)d_out;

    const int Bn = in_sizes[0] / (T_DIM * KSZ);   // 512
    const int smem_bytes = (BM * AS_STRIDE + NSZ * WS_STRIDE + NSZ) * (int)sizeof(float); // 52736

    cudaFuncSetAttribute(parallel_linear_tf32_kernel,
                         cudaFuncAttributeMaxDynamicSharedMemorySize, smem_bytes);

    dim3 grid(Bn / BM, T_DIM);   // m-block fastest -> 4 CTAs sharing W_t co-scheduled
    parallel_linear_tf32_kernel<<<grid, 256, smem_bytes>>>(x, W, b, out);
}

// round 3
// speedup vs baseline: 1.0406x; 1.0406x over previous
#include <cuda_runtime.h>
#include <cstdint>

#define T_DIM 1024
#define KSZ   64
#define NSZ   64
#define BM    128

#define AS_STRIDE 68 // padded smem row stride (words) -> conflict-free scalar frag loads
#define WS_STRIDE 68

__device__ __forceinline__ uint32_t f2tf32(float f) {
    uint32_t r;
    asm("cvt.rna.tf32.f32 %0, %1;" : "=r"(r) : "f"(f));
    return r;
}

__global__ __launch_bounds__(256, 3)
void parallel_linear_tf32_kernel(const float* __restrict__ x,
                                 const float* __restrict__ W,
                                 const float* __restrict__ bias,
                                 float* __restrict__ out)
{
    extern __shared__ uint32_t smem[];
    uint32_t* sA = smem;                       // BM  x AS_STRIDE (tf32 bits)
    uint32_t* sW = smem + BM * AS_STRIDE;      // NSZ x WS_STRIDE (tf32 bits)
    float*    sB = reinterpret_cast<float*>(sW + NSZ * WS_STRIDE); // 64 floats

    const int t   = blockIdx.y;
    const int b0  = blockIdx.x * BM;
    const int tid = threadIdx.x;

    // ---- stage W_t [64,64]: float4 gmem load -> cvt.rna in regs -> tf32 smem ----
    {
        const float4* Wg = reinterpret_cast<const float4*>(W + (size_t)t * (NSZ * KSZ));
        #pragma unroll
        for (int i = 0; i < 4; i++) {
            int idx = tid + i * 256;
            int row = idx >> 4;
            int c4  = idx & 15;
            float4 v = Wg[row * 16 + c4];
            uint4 u = make_uint4(f2tf32(v.x), f2tf32(v.y), f2tf32(v.z), f2tf32(v.w));
            *reinterpret_cast<uint4*>(&sW[row * WS_STRIDE + c4 * 4]) = u;
        }
    }
    // ---- stage X tile [128,64]: rows strided by T*64 in gmem ----
    {
        const float* xg = x + ((size_t)b0 * T_DIM + t) * KSZ;
        #pragma unroll
        for (int i = 0; i < 8; i++) {
            int idx = tid + i * 256;
            int row = idx >> 4;
            int c4  = idx & 15;
            float4 v = *reinterpret_cast<const float4*>(
                xg + (size_t)row * (T_DIM * KSZ) + c4 * 4);
            uint4 u = make_uint4(f2tf32(v.x), f2tf32(v.y), f2tf32(v.z), f2tf32(v.w));
            *reinterpret_cast<uint4*>(&sA[row * AS_STRIDE + c4 * 4]) = u;
        }
    }
    if (tid < NSZ) sB[tid] = bias[t * NSZ + tid];
    __syncthreads();

    const int warp = tid >> 5;
    const int lane = tid & 31;
    const int g    = lane >> 2;     // groupID
    const int tg   = lane & 3;      // thread in group
    const int mrow = warp * 16 + g;

    float acc[8][4];
    #pragma unroll
    for (int n = 0; n < 8; n++)
        #pragma unroll
        for (int j = 0; j < 4; j++) acc[n][j] = 0.f;

    const uint32_t* pA0 = sA +  mrow      * AS_STRIDE + tg;
    const uint32_t* pA1 = sA + (mrow + 8) * AS_STRIDE + tg;
    const uint32_t* pW  = sW + g * WS_STRIDE + tg;   // + nt*8*WS_STRIDE + k0

    // ---- mainloop: K=64 as 8 steps of m16n8k8 tf32 mma (no cvt, pure LDS+MMA) ----
    #pragma unroll
    for (int ks = 0; ks < 8; ks++) {
        const int k0 = ks * 8;
        uint32_t a0 = pA0[k0];
        uint32_t a1 = pA1[k0];
        uint32_t a2 = pA0[k0 + 4];
        uint32_t a3 = pA1[k0 + 4];

        #pragma unroll
        for (int nt = 0; nt < 8; nt++) {
            uint32_t br0 = pW[nt * 8 * WS_STRIDE + k0];
            uint32_t br1 = pW[nt * 8 * WS_STRIDE + k0 + 4];
            asm volatile(
                "mma.sync.aligned.m16n8k8.row.col.f32.tf32.tf32.f32 "
                "{%0,%1,%2,%3}, {%4,%5,%6,%7}, {%8,%9}, {%0,%1,%2,%3};"
                : "+f"(acc[nt][0]), "+f"(acc[nt][1]),
                  "+f"(acc[nt][2]), "+f"(acc[nt][3])
                : "r"(a0), "r"(a1), "r"(a2), "r"(a3), "r"(br0), "r"(br1));
        }
    }

    // ---- epilogue: +bias, float2 stores ----
    const size_t row_stride = (size_t)T_DIM * KSZ;
    #pragma unroll
    for (int nt = 0; nt < 8; nt++) {
        const int col = nt * 8 + 2 * tg;
        const float bs0 = sB[col];
        const float bs1 = sB[col + 1];
        size_t base = ((size_t)(b0 + mrow) * T_DIM + t) * KSZ + col;
        float2 v0 = make_float2(acc[nt][0] + bs0, acc[nt][1] + bs1);
        *reinterpret_cast<float2*>(out + base) = v0;
        float2 v1 = make_float2(acc[nt][2] + bs0, acc[nt][3] + bs1);
        *reinterpret_cast<float2*>(out + base + 8 * row_stride) = v1;
    }
}

extern "C" void kernel_launch(void* const* d_in, const int* in_sizes, int n_in,
                              void* d_out, int out_size)
{
    const float* x = (const float*)d_in[0];
    const float* W = (const float*)d_in[1];
    const float* b = (const float*)d_in[2];
    float* out     = (float*)d_out;

    const int Bn = in_sizes[0] / (T_DIM * KSZ);
    const int smem_bytes = (BM * AS_STRIDE + NSZ * WS_STRIDE + NSZ) * (int)sizeof(uint32_t);

    cudaFuncSetAttribute(parallel_linear_tf32_kernel,
                         cudaFuncAttributeMaxDynamicSharedMemorySize, smem_bytes);

    dim3 grid(Bn / BM, T_DIM);
    parallel_linear_tf32_kernel<<<grid, 256, smem_bytes>>>(x, W, b, out);
}

// round 5
// speedup vs baseline: 1.1474x; 1.1027x over previous
#include <cuda_runtime.h>
#include <cstdint>

#define T_DIM  1024
#define KSZ    64
#define NSZ    64
#define CHUNK  128      // batch rows per pipeline stage
#define NCHUNK 4        // 512 / 128
#define STR    68       // padded smem row stride (words) -> conflict-free frag LDS

__device__ __forceinline__ uint32_t f2tf32(float f) {
    uint32_t r; asm("cvt.rna.tf32.f32 %0, %1;" : "=r"(r) : "f"(f)); return r;
}
__device__ __forceinline__ uint32_t smem_u32(const void* p) {
    uint32_t a;
    asm("{ .reg .u64 t; cvta.to.shared.u64 t, %1; cvt.u32.u64 %0, t; }" : "=r"(a) : "l"(p));
    return a;
}
__device__ __forceinline__ void cp_async16(uint32_t dst, const void* src) {
    asm volatile("cp.async.cg.shared.global [%0], [%1], 16;" :: "r"(dst), "l"(src));
}

__global__ __launch_bounds__(256, 2)
void parallel_linear_pipe(const float* __restrict__ x,
                          const float* __restrict__ W,
                          const float* __restrict__ bias,
                          float* __restrict__ out)
{
    extern __shared__ float smem[];
    float*    sA[2] = { smem, smem + CHUNK * STR };      // fp32 X chunks (double buffer)
    uint32_t* sW    = reinterpret_cast<uint32_t*>(smem + 2 * CHUNK * STR); // tf32 bits
    float*    sB    = reinterpret_cast<float*>(sW + NSZ * STR);

    const int t    = blockIdx.x;
    const int tid  = threadIdx.x;
    const int warp = tid >> 5;
    const int lane = tid & 31;
    const int g    = lane >> 2;          // groupID 0..7
    const int tg   = lane & 3;           // thread-in-group 0..3
    const int nhalf  = warp & 1;         // which 32 output cols
    const int mgroup = warp >> 1;        // which 32 rows within a chunk

    const size_t rowstride = (size_t)T_DIM * KSZ;

    // ---- prologue: issue cp.async for chunks 0 and 1 ----
    #pragma unroll
    for (int cc = 0; cc < 2; cc++) {
        #pragma unroll
        for (int i = 0; i < 8; i++) {
            int idx = tid + i * 256;         // float4 id 0..2047
            int r   = idx >> 4;              // row in chunk
            int c4  = idx & 15;
            const float* src = x + ((size_t)(cc * CHUNK + r) * T_DIM + t) * KSZ + c4 * 4;
            cp_async16(smem_u32(&sA[cc][r * STR + c4 * 4]), src);
        }
        asm volatile("cp.async.commit_group;");
    }

    // ---- stage W_t [64,64] -> tf32 bits in smem (overlaps with async X loads) ----
    {
        const float4* Wg = reinterpret_cast<const float4*>(W + (size_t)t * (NSZ * KSZ));
        #pragma unroll
        for (int i = 0; i < 4; i++) {
            int idx = tid + i * 256;
            int n   = idx >> 4;
            int c4  = idx & 15;
            float4 v = Wg[n * 16 + c4];
            uint4 u = make_uint4(f2tf32(v.x), f2tf32(v.y), f2tf32(v.z), f2tf32(v.w));
            *reinterpret_cast<uint4*>(&sW[n * STR + c4 * 4]) = u;
        }
    }
    if (tid < NSZ) sB[tid] = bias[t * NSZ + tid];
    __syncthreads();

    // ---- load W fragments ONCE into registers (reused for all 512 rows) ----
    uint32_t wf0[4][8], wf1[4][8];           // [n-tile][k-step]
    #pragma unroll
    for (int nt = 0; nt < 4; nt++) {
        const int ncol = nhalf * 32 + nt * 8 + g;
        #pragma unroll
        for (int ks = 0; ks < 8; ks++) {
            wf0[nt][ks] = sW[ncol * STR + ks * 8 + tg];
            wf1[nt][ks] = sW[ncol * STR + ks * 8 + tg + 4];
        }
    }
    float bb0[4], bb1[4];
    #pragma unroll
    for (int nt = 0; nt < 4; nt++) {
        bb0[nt] = sB[nhalf * 32 + nt * 8 + 2 * tg];
        bb1[nt] = sB[nhalf * 32 + nt * 8 + 2 * tg + 1];
    }

    // ---- pipelined mainloop over 4 chunks ----
    #pragma unroll
    for (int c = 0; c < NCHUNK; c++) {
        if (c < NCHUNK - 1) asm volatile("cp.async.wait_group 1;");
        else                asm volatile("cp.async.wait_group 0;");
        __syncthreads();

        const float* aBuf = sA[c & 1];

        #pragma unroll
        for (int tile = 0; tile < 2; tile++) {
            const int rb = mgroup * 32 + tile * 16;   // tile row base within chunk
            float acc[4][4];
            #pragma unroll
            for (int nt = 0; nt < 4; nt++)
                #pragma unroll
                for (int j = 0; j < 4; j++) acc[nt][j] = 0.f;

            #pragma unroll
            for (int ks = 0; ks < 8; ks++) {
                const int k0 = ks * 8;
                uint32_t a0 = f2tf32(aBuf[(rb + g)     * STR + k0 + tg]);
                uint32_t a1 = f2tf32(aBuf[(rb + 8 + g) * STR + k0 + tg]);
                uint32_t a2 = f2tf32(aBuf[(rb + g)     * STR + k0 + tg + 4]);
                uint32_t a3 = f2tf32(aBuf[(rb + 8 + g) * STR + k0 + tg + 4]);
                #pragma unroll
                for (int nt = 0; nt < 4; nt++) {
                    asm volatile(
                        "mma.sync.aligned.m16n8k8.row.col.f32.tf32.tf32.f32 "
                        "{%0,%1,%2,%3}, {%4,%5,%6,%7}, {%8,%9}, {%0,%1,%2,%3};"
                        : "+f"(acc[nt][0]), "+f"(acc[nt][1]),
                          "+f"(acc[nt][2]), "+f"(acc[nt][3])
                        : "r"(a0), "r"(a1), "r"(a2), "r"(a3),
                          "r"(wf0[nt][ks]), "r"(wf1[nt][ks]));
                }
            }

            // epilogue: +bias, float2 stores (8 rows x 32B per instr, coalesced sectors)
            const int grow = c * CHUNK + rb + g;
            #pragma unroll
            for (int nt = 0; nt < 4; nt++) {
                const int col = nhalf * 32 + nt * 8 + 2 * tg;
                size_t base = ((size_t)grow * T_DIM + t) * KSZ + col;
                *reinterpret_cast<float2*>(out + base) =
                    make_float2(acc[nt][0] + bb0[nt], acc[nt][1] + bb1[nt]);
                *reinterpret_cast<float2*>(out + base + 8 * rowstride) =
                    make_float2(acc[nt][2] + bb0[nt], acc[nt][3] + bb1[nt]);
            }
        }
        __syncthreads();   // all warps done with aBuf before it is refilled

        if (c + 2 < NCHUNK) {
            float* dst = sA[c & 1];
            #pragma unroll
            for (int i = 0; i < 8; i++) {
                int idx = tid + i * 256;
                int r   = idx >> 4;
                int c4  = idx & 15;
                const float* src =
                    x + ((size_t)((c + 2) * CHUNK + r) * T_DIM + t) * KSZ + c4 * 4;
                cp_async16(smem_u32(&dst[r * STR + c4 * 4]), src);
            }
            asm volatile("cp.async.commit_group;");
        }
    }
}

extern "C" void kernel_launch(void* const* d_in, const int* in_sizes, int n_in,
                              void* d_out, int out_size)
{
    const float* x = (const float*)d_in[0];
    const float* W = (const float*)d_in[1];
    const float* b = (const float*)d_in[2];
    float* out     = (float*)d_out;

    const int smem_bytes =
        (2 * CHUNK * STR + NSZ * STR + NSZ) * (int)sizeof(float);  // 87296

    cudaFuncSetAttribute(parallel_linear_pipe,
                         cudaFuncAttributeMaxDynamicSharedMemorySize, smem_bytes);

    parallel_linear_pipe<<<T_DIM, 256, smem_bytes>>>(x, W, b, out);
}